// round 1
// baseline (speedup 1.0000x reference)
#include <cuda_runtime.h>

// Problem constants
#define BQ 4
#define NQ 2048
#define DQ 512
#define PQ 16
#define KQ 4
#define KDQ (KQ*DQ)

// Scratch: proj[b][k][j][d], field[b][k][i][d]  (each 64 MB fp32)
__device__ float g_proj [BQ*KQ*NQ*DQ];
__device__ float g_field[BQ*KQ*NQ*DQ];

// ---------------------------------------------------------------------------
// Kernel A: projection GEMM.  proj[b,k,j,d] = sum_c charge[b,j,c] * Wch[k*D+d, c]
// 128x128 tile, kstep 8, 256 threads, 8x8 per thread.
// ---------------------------------------------------------------------------
__global__ __launch_bounds__(256) void proj_gemm_kernel(
    const float* __restrict__ charge, const float* __restrict__ Wch)
{
    const int b  = blockIdx.z;
    const int j0 = blockIdx.x * 128;
    const int n0 = blockIdx.y * 128;   // kd tile base
    const int t  = threadIdx.x;
    const int tx = t & 15, ty = t >> 4;

    __shared__ float As[8][128];
    __shared__ float Bs[8][128];

    float acc[8][8];
#pragma unroll
    for (int r = 0; r < 8; r++)
#pragma unroll
        for (int q = 0; q < 8; q++) acc[r][q] = 0.0f;

    const float* Abase = charge + (b*NQ + j0)*DQ;

    for (int c0 = 0; c0 < DQ; c0 += 8) {
        // load A tile (128 rows x 8 c)
        {
            int jj = t >> 1, cgp = t & 1;
            float4 v = *(const float4*)(Abase + jj*DQ + c0 + cgp*4);
            As[cgp*4+0][jj] = v.x; As[cgp*4+1][jj] = v.y;
            As[cgp*4+2][jj] = v.z; As[cgp*4+3][jj] = v.w;
        }
        // load B tile: Bs[cc][kdj] = Wch[(n0+kdj)*D + c0+cc]
        {
            int kdj = t & 127, cgp = t >> 7;
            float4 v = *(const float4*)(Wch + (n0+kdj)*DQ + c0 + cgp*4);
            Bs[cgp*4+0][kdj] = v.x; Bs[cgp*4+1][kdj] = v.y;
            Bs[cgp*4+2][kdj] = v.z; Bs[cgp*4+3][kdj] = v.w;
        }
        __syncthreads();
#pragma unroll
        for (int kk = 0; kk < 8; kk++) {
            float a[8], bb[8];
            *(float4*)&a[0]  = *(const float4*)&As[kk][ty*8];
            *(float4*)&a[4]  = *(const float4*)&As[kk][ty*8+4];
            *(float4*)&bb[0] = *(const float4*)&Bs[kk][tx*4];
            *(float4*)&bb[4] = *(const float4*)&Bs[kk][64 + tx*4];
#pragma unroll
            for (int r = 0; r < 8; r++)
#pragma unroll
                for (int q = 0; q < 8; q++)
                    acc[r][q] += a[r]*bb[q];
        }
        __syncthreads();
    }

    // scatter to proj[b][k][j][d]
    const int c1 = n0 + tx*4;
    const int c2 = c1 + 64;
    const int k1 = c1 >> 9, d1 = c1 & 511;
    const int k2 = c2 >> 9, d2 = c2 & 511;
#pragma unroll
    for (int r = 0; r < 8; r++) {
        int j = j0 + ty*8 + r;
        *(float4*)(g_proj + ((b*KQ + k1)*NQ + j)*DQ + d1) =
            make_float4(acc[r][0], acc[r][1], acc[r][2], acc[r][3]);
        *(float4*)(g_proj + ((b*KQ + k2)*NQ + j)*DQ + d2) =
            make_float4(acc[r][4], acc[r][5], acc[r][6], acc[r][7]);
    }
}

// ---------------------------------------------------------------------------
// Kernel B: field[b,k,i,d] = sum_j exp(-d2(i,j)*ck)*mass[j] * proj[b,k,j,d]
// Block = (b, k, i-tile of 64) x full D=512. 512 threads.
// Thread: 8 rows (rg) x 8 cols (cg, split 4+4 for conflict-free LDS).
// Weights computed once per j-tile into smem (exp on MUFU, hidden under FFMA).
// ---------------------------------------------------------------------------
__global__ __launch_bounds__(512) void field_kernel(
    const float* __restrict__ position, const float* __restrict__ mass,
    const float* __restrict__ lbw)
{
    const int b  = blockIdx.z;
    const int k  = blockIdx.y;
    const int i0 = blockIdx.x * 64;
    const int t  = threadIdx.x;
    const int rg = t >> 6;      // 0..7  -> rows rg*8 + r
    const int cg = t & 63;      // cols cg*4+q and 256+cg*4+q

    __shared__ float posI[64*17];
    __shared__ float posJ[16*17];
    __shared__ float massJ[16];
    __shared__ float wS[16*64];       // wS[j][i]
    __shared__ float projS[16*512];   // projS[j][d]

    const float bw   = __expf(lbw[k]);
    const float negc = -1.0f / (2.0f*bw + 1e-8f);

    // load query positions once
    for (int u = t; u < 64*16; u += 512) {
        int i = u >> 4, p = u & 15;
        posI[i*17+p] = position[(b*NQ + i0 + i)*PQ + p];
    }

    float acc[8][8];
#pragma unroll
    for (int r = 0; r < 8; r++)
#pragma unroll
        for (int q = 0; q < 8; q++) acc[r][q] = 0.0f;

    const float* projBase = g_proj + (size_t)(b*KQ + k)*NQ*DQ;

    for (int jt = 0; jt < NQ/16; jt++) {
        const int j0 = jt*16;
        __syncthreads();   // guard smem reuse from previous iteration
        // load key positions + mass
        if (t < 256) {
            int j = t >> 4, p = t & 15;
            posJ[j*17+p] = position[(b*NQ + j0 + j)*PQ + p];
        }
        if (t < 16) massJ[t] = mass[b*NQ + j0 + t];
        // load proj tile 16 x 512 (each thread one 64B chunk of one row)
        {
            int jj = t >> 5, cb = (t & 31)*16;
            const float* src = projBase + (j0 + jj)*DQ + cb;
            float4 v0 = *(const float4*)(src + 0);
            float4 v1 = *(const float4*)(src + 4);
            float4 v2 = *(const float4*)(src + 8);
            float4 v3 = *(const float4*)(src + 12);
            *(float4*)&projS[jj*512 + cb + 0]  = v0;
            *(float4*)&projS[jj*512 + cb + 4]  = v1;
            *(float4*)&projS[jj*512 + cb + 8]  = v2;
            *(float4*)&projS[jj*512 + cb + 12] = v3;
        }
        __syncthreads();
        // compute weights: 1024 values, 2 per thread
#pragma unroll
        for (int u0 = 0; u0 < 2; u0++) {
            int u = t + u0*512;
            int j = u >> 6, i = u & 63;
            float d2 = 0.0f;
#pragma unroll
            for (int p = 0; p < 16; p++) {
                float df = posI[i*17+p] - posJ[j*17+p];
                d2 += df*df;
            }
            wS[j*64 + i] = __expf(d2*negc) * massJ[j];
        }
        __syncthreads();
        // outer-product accumulation
#pragma unroll
        for (int jj = 0; jj < 16; jj++) {
            float wv[8], pv[8];
            *(float4*)&wv[0] = *(const float4*)&wS[jj*64 + rg*8];
            *(float4*)&wv[4] = *(const float4*)&wS[jj*64 + rg*8 + 4];
            *(float4*)&pv[0] = *(const float4*)&projS[jj*512 + cg*4];
            *(float4*)&pv[4] = *(const float4*)&projS[jj*512 + 256 + cg*4];
#pragma unroll
            for (int r = 0; r < 8; r++)
#pragma unroll
                for (int q = 0; q < 8; q++)
                    acc[r][q] += wv[r]*pv[q];
        }
    }

    float* fBase = g_field + (size_t)(b*KQ + k)*NQ*DQ;
#pragma unroll
    for (int r = 0; r < 8; r++) {
        int i = i0 + rg*8 + r;
        *(float4*)(fBase + i*DQ + cg*4) =
            make_float4(acc[r][0], acc[r][1], acc[r][2], acc[r][3]);
        *(float4*)(fBase + i*DQ + 256 + cg*4) =
            make_float4(acc[r][4], acc[r][5], acc[r][6], acc[r][7]);
    }
}

// ---------------------------------------------------------------------------
// Kernel C: out[b,i,:] = LN( sum_kd field[b,i,kd] * Wcb[dout,kd] ) * gamma + beta
// Block = (b, i-tile of 32) x full dout=512. 256 threads, 8x8 per thread.
// ---------------------------------------------------------------------------
__global__ __launch_bounds__(256) void combine_ln_kernel(
    const float* __restrict__ Wcb, const float* __restrict__ gammaP,
    const float* __restrict__ betaP, float* __restrict__ out)
{
    const int b  = blockIdx.y;
    const int i0 = blockIdx.x * 32;
    const int t  = threadIdx.x;
    const int rg = t >> 6;     // 0..3 -> rows rg*8+r
    const int cg = t & 63;     // cols cg*4+q and 256+cg*4+q

    __shared__ float fieldT[16*40];   // fieldT[kk][i], padded
    __shared__ float WcS[16*516];     // WcS[kk][dout], padded
    __shared__ float meanS[32], rsS[32];
    __shared__ float gammaS[512], betaS[512];

    for (int u = t; u < 512; u += 256) { gammaS[u] = gammaP[u]; betaS[u] = betaP[u]; }

    float acc[8][8];
#pragma unroll
    for (int r = 0; r < 8; r++)
#pragma unroll
        for (int q = 0; q < 8; q++) acc[r][q] = 0.0f;

    for (int kt = 0; kt < KDQ/16; kt++) {
        const int kd0 = kt*16;
        const int k   = kd0 >> 9;
        const int d0  = kd0 & 511;
        __syncthreads();
        // field tile 32 rows x 16 kd, transposed into smem
#pragma unroll
        for (int m = 0; m < 2; m++) {
            int u = t + m*256;
            int i = u >> 4, kk = u & 15;
            fieldT[kk*40 + i] = g_field[((size_t)(b*KQ + k)*NQ + i0 + i)*DQ + d0 + kk];
        }
        // Wcb tile 16 kd x 512 dout, transposed into smem
#pragma unroll
        for (int m = 0; m < 8; m++) {
            int u = t + m*256;
            int dout = u >> 2, q = u & 3;
            float4 v = *(const float4*)(Wcb + dout*KDQ + kd0 + q*4);
            WcS[(q*4+0)*516 + dout] = v.x;
            WcS[(q*4+1)*516 + dout] = v.y;
            WcS[(q*4+2)*516 + dout] = v.z;
            WcS[(q*4+3)*516 + dout] = v.w;
        }
        __syncthreads();
#pragma unroll
        for (int kk = 0; kk < 16; kk++) {
            float a[8], bb[8];
            *(float4*)&a[0]  = *(const float4*)&fieldT[kk*40 + rg*8];
            *(float4*)&a[4]  = *(const float4*)&fieldT[kk*40 + rg*8 + 4];
            *(float4*)&bb[0] = *(const float4*)&WcS[kk*516 + cg*4];
            *(float4*)&bb[4] = *(const float4*)&WcS[kk*516 + 256 + cg*4];
#pragma unroll
            for (int r = 0; r < 8; r++)
#pragma unroll
                for (int q = 0; q < 8; q++)
                    acc[r][q] += a[r]*bb[q];
        }
    }

    // ---- LayerNorm ----
    __syncthreads();
    float* rowSum = WcS;          // reuse smem (done with WcS)
    float* rowSq  = WcS + 2048;
#pragma unroll
    for (int r = 0; r < 8; r++) {
        float s = 0.0f, s2 = 0.0f;
#pragma unroll
        for (int q = 0; q < 8; q++) { s += acc[r][q]; s2 += acc[r][q]*acc[r][q]; }
        int row = rg*8 + r;
        rowSum[row*64 + cg] = s;
        rowSq [row*64 + cg] = s2;
    }
    __syncthreads();
    {
        int w = t >> 5, lane = t & 31;
#pragma unroll
        for (int rr = 0; rr < 4; rr++) {
            int row = w*4 + rr;
            float s  = rowSum[row*64 + lane] + rowSum[row*64 + lane + 32];
            float s2 = rowSq [row*64 + lane] + rowSq [row*64 + lane + 32];
#pragma unroll
            for (int off = 16; off > 0; off >>= 1) {
                s  += __shfl_xor_sync(0xffffffffu, s,  off);
                s2 += __shfl_xor_sync(0xffffffffu, s2, off);
            }
            if (lane == 0) {
                float mean = s * (1.0f/512.0f);
                float var  = s2 * (1.0f/512.0f) - mean*mean;
                meanS[row] = mean;
                rsS[row]   = rsqrtf(var + 1e-5f);
            }
        }
    }
    __syncthreads();
#pragma unroll
    for (int r = 0; r < 8; r++) {
        int row = rg*8 + r;
        float m  = meanS[row];
        float rs = rsS[row];
        float o[8];
#pragma unroll
        for (int q = 0; q < 4; q++) {
            int col = cg*4 + q;
            o[q]   = (acc[r][q]   - m)*rs*gammaS[col]       + betaS[col];
            o[q+4] = (acc[r][q+4] - m)*rs*gammaS[col + 256] + betaS[col + 256];
        }
        float* dst = out + (size_t)(b*NQ + i0 + row)*DQ;
        *(float4*)(dst + cg*4)       = make_float4(o[0], o[1], o[2], o[3]);
        *(float4*)(dst + 256 + cg*4) = make_float4(o[4], o[5], o[6], o[7]);
    }
}

// ---------------------------------------------------------------------------
extern "C" void kernel_launch(void* const* d_in, const int* in_sizes, int n_in,
                              void* d_out, int out_size)
{
    const float* charge   = (const float*)d_in[0];
    const float* position = (const float*)d_in[1];
    const float* mass     = (const float*)d_in[2];
    const float* lbw      = (const float*)d_in[3];
    const float* Wch      = (const float*)d_in[4];
    const float* Wcb      = (const float*)d_in[5];
    const float* gammaP   = (const float*)d_in[6];
    const float* betaP    = (const float*)d_in[7];
    float* out = (float*)d_out;

    proj_gemm_kernel <<<dim3(NQ/128, KDQ/128, BQ), 256>>>(charge, Wch);
    field_kernel     <<<dim3(NQ/64, KQ, BQ), 512>>>(position, mass, lbw);
    combine_ln_kernel<<<dim3(NQ/32, BQ), 256>>>(Wcb, gammaP, betaP, out);
}

// round 2
// speedup vs baseline: 1.0007x; 1.0007x over previous
#include <cuda_runtime.h>

// Problem constants
#define BQ 4
#define NQ 2048
#define DQ 512
#define PQ 16
#define KQ 4
#define KDQ (KQ*DQ)

// Scratch: proj[b][k][j][d], field[b][k][i][d]  (each 64 MB fp32)
__device__ float g_proj [BQ*KQ*NQ*DQ];
__device__ float g_field[BQ*KQ*NQ*DQ];

// ---------------------------------------------------------------------------
// Kernel A: projection GEMM.  proj[b,k,j,d] = sum_c charge[b,j,c] * Wch[k*D+d, c]
// 128x128 tile, kstep 8, 256 threads, 8x8 per thread.
// ---------------------------------------------------------------------------
__global__ __launch_bounds__(256) void proj_gemm_kernel(
    const float* __restrict__ charge, const float* __restrict__ Wch)
{
    const int b  = blockIdx.z;
    const int j0 = blockIdx.x * 128;
    const int n0 = blockIdx.y * 128;   // kd tile base
    const int t  = threadIdx.x;
    const int tx = t & 15, ty = t >> 4;

    __shared__ float As[8][128];
    __shared__ float Bs[8][128];

    float acc[8][8];
#pragma unroll
    for (int r = 0; r < 8; r++)
#pragma unroll
        for (int q = 0; q < 8; q++) acc[r][q] = 0.0f;

    const float* Abase = charge + (b*NQ + j0)*DQ;

    for (int c0 = 0; c0 < DQ; c0 += 8) {
        // load A tile (128 rows x 8 c)
        {
            int jj = t >> 1, cgp = t & 1;
            float4 v = *(const float4*)(Abase + jj*DQ + c0 + cgp*4);
            As[cgp*4+0][jj] = v.x; As[cgp*4+1][jj] = v.y;
            As[cgp*4+2][jj] = v.z; As[cgp*4+3][jj] = v.w;
        }
        // load B tile: Bs[cc][kdj] = Wch[(n0+kdj)*D + c0+cc]
        {
            int kdj = t & 127, cgp = t >> 7;
            float4 v = *(const float4*)(Wch + (n0+kdj)*DQ + c0 + cgp*4);
            Bs[cgp*4+0][kdj] = v.x; Bs[cgp*4+1][kdj] = v.y;
            Bs[cgp*4+2][kdj] = v.z; Bs[cgp*4+3][kdj] = v.w;
        }
        __syncthreads();
#pragma unroll
        for (int kk = 0; kk < 8; kk++) {
            float a[8], bb[8];
            *(float4*)&a[0]  = *(const float4*)&As[kk][ty*8];
            *(float4*)&a[4]  = *(const float4*)&As[kk][ty*8+4];
            *(float4*)&bb[0] = *(const float4*)&Bs[kk][tx*4];
            *(float4*)&bb[4] = *(const float4*)&Bs[kk][64 + tx*4];
#pragma unroll
            for (int r = 0; r < 8; r++)
#pragma unroll
                for (int q = 0; q < 8; q++)
                    acc[r][q] += a[r]*bb[q];
        }
        __syncthreads();
    }

    // scatter to proj[b][k][j][d]
    const int c1 = n0 + tx*4;
    const int c2 = c1 + 64;
    const int k1 = c1 >> 9, d1 = c1 & 511;
    const int k2 = c2 >> 9, d2 = c2 & 511;
#pragma unroll
    for (int r = 0; r < 8; r++) {
        int j = j0 + ty*8 + r;
        *(float4*)(g_proj + ((b*KQ + k1)*NQ + j)*DQ + d1) =
            make_float4(acc[r][0], acc[r][1], acc[r][2], acc[r][3]);
        *(float4*)(g_proj + ((b*KQ + k2)*NQ + j)*DQ + d2) =
            make_float4(acc[r][4], acc[r][5], acc[r][6], acc[r][7]);
    }
}

// ---------------------------------------------------------------------------
// Kernel B: field[b,k,i,d] = sum_j exp(-d2(i,j)*ck)*mass[j] * proj[b,k,j,d]
// Block = (b, k, i-tile of 64) x full D=512. 512 threads.
// Thread: 8 rows (rg) x 8 cols (cg, split 4+4 for conflict-free LDS).
// Weights computed once per j-tile into smem (exp on MUFU, hidden under FFMA).
// ---------------------------------------------------------------------------
__global__ __launch_bounds__(512) void field_kernel(
    const float* __restrict__ position, const float* __restrict__ mass,
    const float* __restrict__ lbw)
{
    const int b  = blockIdx.z;
    const int k  = blockIdx.y;
    const int i0 = blockIdx.x * 64;
    const int t  = threadIdx.x;
    const int rg = t >> 6;      // 0..7  -> rows rg*8 + r
    const int cg = t & 63;      // cols cg*4+q and 256+cg*4+q

    __shared__ float posI[64*17];
    __shared__ float posJ[16*17];
    __shared__ float massJ[16];
    __shared__ float wS[16*64];       // wS[j][i]
    __shared__ float projS[16*512];   // projS[j][d]

    const float bw   = __expf(lbw[k]);
    const float negc = -1.0f / (2.0f*bw + 1e-8f);

    // load query positions once
    for (int u = t; u < 64*16; u += 512) {
        int i = u >> 4, p = u & 15;
        posI[i*17+p] = position[(b*NQ + i0 + i)*PQ + p];
    }

    float acc[8][8];
#pragma unroll
    for (int r = 0; r < 8; r++)
#pragma unroll
        for (int q = 0; q < 8; q++) acc[r][q] = 0.0f;

    const float* projBase = g_proj + (size_t)(b*KQ + k)*NQ*DQ;

    for (int jt = 0; jt < NQ/16; jt++) {
        const int j0 = jt*16;
        __syncthreads();   // guard smem reuse from previous iteration
        // load key positions + mass
        if (t < 256) {
            int j = t >> 4, p = t & 15;
            posJ[j*17+p] = position[(b*NQ + j0 + j)*PQ + p];
        }
        if (t < 16) massJ[t] = mass[b*NQ + j0 + t];
        // load proj tile 16 x 512 (each thread one 64B chunk of one row)
        {
            int jj = t >> 5, cb = (t & 31)*16;
            const float* src = projBase + (j0 + jj)*DQ + cb;
            float4 v0 = *(const float4*)(src + 0);
            float4 v1 = *(const float4*)(src + 4);
            float4 v2 = *(const float4*)(src + 8);
            float4 v3 = *(const float4*)(src + 12);
            *(float4*)&projS[jj*512 + cb + 0]  = v0;
            *(float4*)&projS[jj*512 + cb + 4]  = v1;
            *(float4*)&projS[jj*512 + cb + 8]  = v2;
            *(float4*)&projS[jj*512 + cb + 12] = v3;
        }
        __syncthreads();
        // compute weights: 1024 values, 2 per thread
#pragma unroll
        for (int u0 = 0; u0 < 2; u0++) {
            int u = t + u0*512;
            int j = u >> 6, i = u & 63;
            float d2 = 0.0f;
#pragma unroll
            for (int p = 0; p < 16; p++) {
                float df = posI[i*17+p] - posJ[j*17+p];
                d2 += df*df;
            }
            wS[j*64 + i] = __expf(d2*negc) * massJ[j];
        }
        __syncthreads();
        // outer-product accumulation
#pragma unroll
        for (int jj = 0; jj < 16; jj++) {
            float wv[8], pv[8];
            *(float4*)&wv[0] = *(const float4*)&wS[jj*64 + rg*8];
            *(float4*)&wv[4] = *(const float4*)&wS[jj*64 + rg*8 + 4];
            *(float4*)&pv[0] = *(const float4*)&projS[jj*512 + cg*4];
            *(float4*)&pv[4] = *(const float4*)&projS[jj*512 + 256 + cg*4];
#pragma unroll
            for (int r = 0; r < 8; r++)
#pragma unroll
                for (int q = 0; q < 8; q++)
                    acc[r][q] += wv[r]*pv[q];
        }
    }

    float* fBase = g_field + (size_t)(b*KQ + k)*NQ*DQ;
#pragma unroll
    for (int r = 0; r < 8; r++) {
        int i = i0 + rg*8 + r;
        *(float4*)(fBase + i*DQ + cg*4) =
            make_float4(acc[r][0], acc[r][1], acc[r][2], acc[r][3]);
        *(float4*)(fBase + i*DQ + 256 + cg*4) =
            make_float4(acc[r][4], acc[r][5], acc[r][6], acc[r][7]);
    }
}

// ---------------------------------------------------------------------------
// Kernel C: out[b,i,:] = LN( sum_kd field[b,i,kd] * Wcb[dout,kd] ) * gamma + beta
// Block = (b, i-tile of 32) x full dout=512. 256 threads, 8x8 per thread.
// ---------------------------------------------------------------------------
__global__ __launch_bounds__(256) void combine_ln_kernel(
    const float* __restrict__ Wcb, const float* __restrict__ gammaP,
    const float* __restrict__ betaP, float* __restrict__ out)
{
    const int b  = blockIdx.y;
    const int i0 = blockIdx.x * 32;
    const int t  = threadIdx.x;
    const int rg = t >> 6;     // 0..3 -> rows rg*8+r
    const int cg = t & 63;     // cols cg*4+q and 256+cg*4+q

    __shared__ float fieldT[16*40];   // fieldT[kk][i], padded
    __shared__ float WcS[16*516];     // WcS[kk][dout], padded
    __shared__ float meanS[32], rsS[32];
    __shared__ float gammaS[512], betaS[512];

    for (int u = t; u < 512; u += 256) { gammaS[u] = gammaP[u]; betaS[u] = betaP[u]; }

    float acc[8][8];
#pragma unroll
    for (int r = 0; r < 8; r++)
#pragma unroll
        for (int q = 0; q < 8; q++) acc[r][q] = 0.0f;

    for (int kt = 0; kt < KDQ/16; kt++) {
        const int kd0 = kt*16;
        const int k   = kd0 >> 9;
        const int d0  = kd0 & 511;
        __syncthreads();
        // field tile 32 rows x 16 kd, transposed into smem
#pragma unroll
        for (int m = 0; m < 2; m++) {
            int u = t + m*256;
            int i = u >> 4, kk = u & 15;
            fieldT[kk*40 + i] = g_field[((size_t)(b*KQ + k)*NQ + i0 + i)*DQ + d0 + kk];
        }
        // Wcb tile 16 kd x 512 dout, transposed into smem
#pragma unroll
        for (int m = 0; m < 8; m++) {
            int u = t + m*256;
            int dout = u >> 2, q = u & 3;
            float4 v = *(const float4*)(Wcb + dout*KDQ + kd0 + q*4);
            WcS[(q*4+0)*516 + dout] = v.x;
            WcS[(q*4+1)*516 + dout] = v.y;
            WcS[(q*4+2)*516 + dout] = v.z;
            WcS[(q*4+3)*516 + dout] = v.w;
        }
        __syncthreads();
#pragma unroll
        for (int kk = 0; kk < 16; kk++) {
            float a[8], bb[8];
            *(float4*)&a[0]  = *(const float4*)&fieldT[kk*40 + rg*8];
            *(float4*)&a[4]  = *(const float4*)&fieldT[kk*40 + rg*8 + 4];
            *(float4*)&bb[0] = *(const float4*)&WcS[kk*516 + cg*4];
            *(float4*)&bb[4] = *(const float4*)&WcS[kk*516 + 256 + cg*4];
#pragma unroll
            for (int r = 0; r < 8; r++)
#pragma unroll
                for (int q = 0; q < 8; q++)
                    acc[r][q] += a[r]*bb[q];
        }
    }

    // ---- LayerNorm ----
    __syncthreads();
    float* rowSum = WcS;          // reuse smem (done with WcS)
    float* rowSq  = WcS + 2048;
#pragma unroll
    for (int r = 0; r < 8; r++) {
        float s = 0.0f, s2 = 0.0f;
#pragma unroll
        for (int q = 0; q < 8; q++) { s += acc[r][q]; s2 += acc[r][q]*acc[r][q]; }
        int row = rg*8 + r;
        rowSum[row*64 + cg] = s;
        rowSq [row*64 + cg] = s2;
    }
    __syncthreads();
    {
        int w = t >> 5, lane = t & 31;
#pragma unroll
        for (int rr = 0; rr < 4; rr++) {
            int row = w*4 + rr;
            float s  = rowSum[row*64 + lane] + rowSum[row*64 + lane + 32];
            float s2 = rowSq [row*64 + lane] + rowSq [row*64 + lane + 32];
#pragma unroll
            for (int off = 16; off > 0; off >>= 1) {
                s  += __shfl_xor_sync(0xffffffffu, s,  off);
                s2 += __shfl_xor_sync(0xffffffffu, s2, off);
            }
            if (lane == 0) {
                float mean = s * (1.0f/512.0f);
                float var  = s2 * (1.0f/512.0f) - mean*mean;
                meanS[row] = mean;
                rsS[row]   = rsqrtf(var + 1e-5f);
            }
        }
    }
    __syncthreads();
#pragma unroll
    for (int r = 0; r < 8; r++) {
        int row = rg*8 + r;
        float m  = meanS[row];
        float rs = rsS[row];
        float o[8];
#pragma unroll
        for (int q = 0; q < 4; q++) {
            int col = cg*4 + q;
            o[q]   = (acc[r][q]   - m)*rs*gammaS[col]       + betaS[col];
            o[q+4] = (acc[r][q+4] - m)*rs*gammaS[col + 256] + betaS[col + 256];
        }
        float* dst = out + (size_t)(b*NQ + i0 + row)*DQ;
        *(float4*)(dst + cg*4)       = make_float4(o[0], o[1], o[2], o[3]);
        *(float4*)(dst + 256 + cg*4) = make_float4(o[4], o[5], o[6], o[7]);
    }
}

// ---------------------------------------------------------------------------
extern "C" void kernel_launch(void* const* d_in, const int* in_sizes, int n_in,
                              void* d_out, int out_size)
{
    const float* charge   = (const float*)d_in[0];
    const float* position = (const float*)d_in[1];
    const float* mass     = (const float*)d_in[2];
    const float* lbw      = (const float*)d_in[3];
    const float* Wch      = (const float*)d_in[4];
    const float* Wcb      = (const float*)d_in[5];
    const float* gammaP   = (const float*)d_in[6];
    const float* betaP    = (const float*)d_in[7];
    float* out = (float*)d_out;

    proj_gemm_kernel <<<dim3(NQ/128, KDQ/128, BQ), 256>>>(charge, Wch);
    field_kernel     <<<dim3(NQ/64, KQ, BQ), 512>>>(position, mass, lbw);
    combine_ln_kernel<<<dim3(NQ/32, BQ), 256>>>(Wcb, gammaP, betaP, out);
}